// round 15
// baseline (speedup 1.0000x reference)
#include <cuda_runtime.h>
#include <cuda_fp16.h>
#include <cstdint>

// Problem dims
#define NL 16
#define DH 128
#define G4 512      // 4*H
#define BB 32
#define TT 512
#define NH 2048     // N*H
#define STRD 136    // padded halves per row (conflict-free LDS)
#define STGW 264    // stage row stride in words

// x_proj scratch, GATE-INTERLEAVED: [n][t][b][j][gate] fp16, bias pre-added
__device__ __half g_xp16[(size_t)NL * TT * BB * G4];
// chunk-ready flags [n][bgroup][chunk of 16 t]; monotonic (stay 1 across replays)
__device__ int g_flags[NL][4][32];

// dynamic SMEM offsets (producer role); consumer uses first 4.4KB as h tiles
#define S_WS   0                 // W_ih fp16 [512][STRD] = 139264
#define S_X0   139264            // x chunk buf0 [128][STRD] = 34816
#define S_X1   174080            // x chunk buf1
#define S_STG  208896            // store stage [2][8][STGW] words = 16896
#define S_TOTAL 225792

// ---------------- mma.sync m16n8k16 (fp16 in, fp32 acc) ----------------
__device__ __forceinline__ void mma16816(float* d, const uint32_t* a,
                                         uint32_t b0, uint32_t b1) {
    asm volatile("mma.sync.aligned.m16n8k16.row.col.f32.f16.f16.f32 "
                 "{%0,%1,%2,%3}, {%4,%5,%6,%7}, {%8,%9}, {%0,%1,%2,%3};"
                 : "+f"(d[0]), "+f"(d[1]), "+f"(d[2]), "+f"(d[3])
                 : "r"(a[0]), "r"(a[1]), "r"(a[2]), "r"(a[3]), "r"(b0), "r"(b1));
}

__device__ __forceinline__ float tanh_apx(float x) {
    float t;
    asm("tanh.approx.f32 %0, %1;" : "=f"(t) : "f"(x));
    return t;
}
__device__ __forceinline__ float sigm_apx(float x) {
    return fmaf(0.5f, tanh_apx(0.5f * x), 0.5f);
}
__device__ __forceinline__ void waitflag(volatile const int* f) {
    if (*f == 0) {
        while (*f == 0) { __nanosleep(200); }
    }
    __threadfence();   // acquire: order subsequent x_proj reads after flag
}

// =================================================================
// COMBO kernel: grid 128 (<=148 -> all CTAs co-resident, distinct SMs).
//   bid 0..63  : PRODUCER (n, bg of 8 batches) — x-projection GEMM,
//                t-chunk-major (16 t x 8 b per chunk), flag per chunk.
//   bid 64..127: CONSUMER (n, bc of 8 batches) — R9 recurrence (measured
//                359us) + flag waits every 16 steps.
// 256 threads both roles.
// =================================================================
__global__ void __launch_bounds__(256, 1) wlstm_combo(
    const float* __restrict__ x, const float* __restrict__ Wih,
    const float* __restrict__ Whh, const float* __restrict__ bih,
    const float* __restrict__ bhh, float* __restrict__ out)
{
    extern __shared__ char smem[];
    const int tid = threadIdx.x, wid = tid >> 5, lane = tid & 31;
    const int g0 = lane >> 2, cq = lane & 3;

    if (blockIdx.x < 64) {
        // ============================ PRODUCER ============================
        const int n = blockIdx.x >> 2, bg = blockIdx.x & 3;
        __half*    ws  = (__half*)(smem + S_WS);
        __half*    xb0 = (__half*)(smem + S_X0);
        __half*    xb1 = (__half*)(smem + S_X1);
        uint32_t*  stw = (uint32_t*)(smem + S_STG);

        // W_ih[n] fp32 -> fp16 SMEM
        const float4* W4 = (const float4*)(Wih + (size_t)n * G4 * DH);
#pragma unroll 8
        for (int i = tid; i < G4 * DH / 4; i += 256) {
            float4 w = W4[i];
            int r = i >> 5, k = (i & 31) * 4;
            __half2 h01 = __floats2half2_rn(w.x, w.y);
            __half2 h23 = __floats2half2_rn(w.z, w.w);
            uint2 v = { *(uint32_t*)&h01, *(uint32_t*)&h23 };
            *(uint2*)(ws + r * STRD + k) = v;
        }

        // x chunk loader: chunk c = 16 t x 8 batches; row r = bl*16 + tl
        auto load_chunk = [&](int c, __half* dst) {
#pragma unroll 4
            for (int i = tid; i < 128 * DH / 4; i += 256) {
                int r = i >> 5, c4 = (i & 31) * 4;
                int b = bg * 8 + (r >> 4), t = c * 16 + (r & 15);
                float4 w = *(const float4*)(x + ((size_t)b * TT + t) * NH + n * DH + c4);
                __half2 h01 = __floats2half2_rn(w.x, w.y);
                __half2 h23 = __floats2half2_rn(w.z, w.w);
                uint2 v = { *(uint32_t*)&h01, *(uint32_t*)&h23 };
                *(uint2*)(dst + r * STRD + c4) = v;
            }
        };
        load_chunk(0, xb0);
        __syncthreads();

        // A-fragments: warp wid owns m-tiles {4wid..4wid+3}
        uint32_t a[4][8][4];
        const uint32_t* ws32 = (const uint32_t*)ws;
#pragma unroll
        for (int ti = 0; ti < 4; ti++) {
            int r0 = (4 * wid + ti) * 16 + g0;
#pragma unroll
            for (int kc = 0; kc < 8; kc++) {
                int kw = kc * 8 + cq;
                a[ti][kc][0] = ws32[r0 * (STRD / 2) + kw];
                a[ti][kc][1] = ws32[(r0 + 8) * (STRD / 2) + kw];
                a[ti][kc][2] = ws32[r0 * (STRD / 2) + kw + 4];
                a[ti][kc][3] = ws32[(r0 + 8) * (STRD / 2) + kw + 4];
            }
        }
        float bsv[4][2];
#pragma unroll
        for (int ti = 0; ti < 4; ti++) {
            int r0 = (4 * wid + ti) * 16 + g0;
            bsv[ti][0] = bih[n * G4 + r0]     + bhh[n * G4 + r0];
            bsv[ti][1] = bih[n * G4 + r0 + 8] + bhh[n * G4 + r0 + 8];
        }

        for (int c = 0; c < 32; c++) {
            const __half* xs = (c & 1) ? xb1 : xb0;
            if (c < 31) load_chunk(c + 1, (c & 1) ? xb0 : xb1);
            const uint32_t* xs32 = (const uint32_t*)xs;

            for (int nt = 0; nt < 16; nt++) {
                uint32_t* stg = stw + (nt & 1) * (8 * STGW);
                __half*   sth = (__half*)stg;
                float d[4][4];
#pragma unroll
                for (int ti = 0; ti < 4; ti++)
#pragma unroll
                    for (int q = 0; q < 4; q++) d[ti][q] = 0.0f;

                int col = nt * 8 + g0;
#pragma unroll
                for (int kc = 0; kc < 8; kc++) {
                    uint32_t b0 = xs32[col * (STRD / 2) + kc * 8 + cq];
                    uint32_t b1 = xs32[col * (STRD / 2) + kc * 8 + cq + 4];
#pragma unroll
                    for (int ti = 0; ti < 4; ti++) mma16816(d[ti], a[ti][kc], b0, b1);
                }
                // stage slice [8 rows][j*4+gate] with bias folded
                int tb0 = 2 * cq;
#pragma unroll
                for (int ti = 0; ti < 4; ti++) {
                    int r0 = (4 * wid + ti) * 16 + g0;
                    int j = r0 & 127, gate = r0 >> 7;
                    sth[(size_t)tb0 * (2 * STGW) + j * 4 + gate]             = __float2half(d[ti][0] + bsv[ti][0]);
                    sth[(size_t)(tb0 + 1) * (2 * STGW) + j * 4 + gate]       = __float2half(d[ti][1] + bsv[ti][0]);
                    sth[(size_t)tb0 * (2 * STGW) + (j + 8) * 4 + gate]       = __float2half(d[ti][2] + bsv[ti][1]);
                    sth[(size_t)(tb0 + 1) * (2 * STGW) + (j + 8) * 4 + gate] = __float2half(d[ti][3] + bsv[ti][1]);
                }
                __syncthreads();
                // cooperative coalesced store: 8 rows x 64 uint4, 2 per thread
                {
                    int tl_s = tid >> 5, w4 = tid & 31;
                    int r = nt * 8 + tl_s;
                    int t = c * 16 + (r & 15), b = bg * 8 + (r >> 4);
                    __half* dro = g_xp16 + ((size_t)(n * TT + t) * BB + b) * G4;
                    uint4 v0 = *(const uint4*)(stg + tl_s * STGW + w4 * 4);
                    uint4 v1 = *(const uint4*)(stg + tl_s * STGW + (w4 + 32) * 4);
                    *(uint4*)(dro + w4 * 8) = v0;
                    *(uint4*)(dro + (w4 + 32) * 8) = v1;
                }
            }
            // publish chunk: every thread fences, barrier, then release flag
            __threadfence();
            __syncthreads();
            if (tid == 0) *(volatile int*)&g_flags[n][bg][c] = 1;
        }
    } else {
        // ============================ CONSUMER ============================
        const int bid = blockIdx.x - 64;
        const int n = bid >> 2, bc = bid & 3;
        __half* hsb = (__half*)smem;   // [2][8][STRD]

        for (int i = tid; i < 2 * 8 * STRD; i += 256) hsb[i] = __float2half(0.0f);

        // W_hh[n] -> A-fragments: gate gi tile rows gi*128 + wid*16
        uint32_t a[4][8][4];
        const float* W = Whh + (size_t)n * G4 * DH;
#pragma unroll
        for (int gi = 0; gi < 4; gi++) {
            int r0 = gi * 128 + wid * 16 + g0;
#pragma unroll
            for (int kc = 0; kc < 8; kc++) {
                int k0 = kc * 16 + cq * 2;
                float2 w00 = *(const float2*)(W + (size_t)r0 * DH + k0);
                float2 w10 = *(const float2*)(W + (size_t)(r0 + 8) * DH + k0);
                float2 w01 = *(const float2*)(W + (size_t)r0 * DH + k0 + 8);
                float2 w11 = *(const float2*)(W + (size_t)(r0 + 8) * DH + k0 + 8);
                __half2 h00 = __floats2half2_rn(w00.x, w00.y);
                __half2 h10 = __floats2half2_rn(w10.x, w10.y);
                __half2 h01 = __floats2half2_rn(w01.x, w01.y);
                __half2 h11 = __floats2half2_rn(w11.x, w11.y);
                a[gi][kc][0] = *(uint32_t*)&h00;
                a[gi][kc][1] = *(uint32_t*)&h10;
                a[gi][kc][2] = *(uint32_t*)&h01;
                a[gi][kc][3] = *(uint32_t*)&h11;
            }
        }

        // states s = jo*2 + bo : j = wid*16 + g0 + jo*8 ; b = bc*8 + 2cq + bo
        const int j0  = wid * 16 + g0;
        const int bl0 = 2 * cq;
        const int bg0 = bc * 8 + bl0;

        const __half* xqb[4];
        float* ob[4];
        int hoff[4];
#pragma unroll
        for (int s = 0; s < 4; s++) {
            int jo = s >> 1, bo = s & 1;
            int j = j0 + jo * 8, b = bg0 + bo;
            xqb[s] = g_xp16 + ((size_t)n * TT * BB + b) * G4 + j * 4;
            ob[s]  = out + (size_t)b * TT * NH + n * DH + j;
            hoff[s] = (bl0 + bo) * STRD + j;
        }

        waitflag(&g_flags[n][bc][0]);

        uint2 xpa[4], xpb[4];
#pragma unroll
        for (int s = 0; s < 4; s++) xpa[s] = *(const uint2*)xqb[s];

        float cst[4], hst[4];
#pragma unroll
        for (int s = 0; s < 4; s++) { cst[s] = 0.0f; hst[s] = 0.0f; }

        __syncthreads();
        size_t toff = 0;

        auto step = [&](int t, uint2 (&xpc)[4], uint2 (&xpn)[4]) {
            if (t + 1 < TT) {
                if (((t + 1) & 15) == 0) waitflag(&g_flags[n][bc][(t + 1) >> 4]);
                size_t xo = (size_t)(t + 1) * (BB * G4);
#pragma unroll
                for (int s = 0; s < 4; s++) xpn[s] = *(const uint2*)(xqb[s] + xo);
            }
            const uint32_t* hb = (const uint32_t*)(hsb + (t & 1) * 8 * STRD);
            float d[4][4];
#pragma unroll
            for (int gi = 0; gi < 4; gi++)
#pragma unroll
                for (int q = 0; q < 4; q++) d[gi][q] = 0.0f;
#pragma unroll
            for (int kc = 0; kc < 8; kc++) {
                uint32_t b0 = hb[g0 * (STRD / 2) + kc * 8 + cq];
                uint32_t b1 = hb[g0 * (STRD / 2) + kc * 8 + cq + 4];
#pragma unroll
                for (int gi = 0; gi < 4; gi++) mma16816(d[gi], a[gi][kc], b0, b1);
            }
            __half* hw = hsb + ((t + 1) & 1) * 8 * STRD;
#pragma unroll
            for (int s = 0; s < 4; s++) {
                int q = s;
                float2 f01 = __half22float2(*(__half2*)&xpc[s].x);
                float2 f23 = __half22float2(*(__half2*)&xpc[s].y);
                float zi = d[0][q] + f01.x;
                float zf = d[1][q] + f01.y;
                float zg = d[2][q] + f23.x;
                float zo = d[3][q] + f23.y;
                float ig = sigm_apx(zi);
                float fg = sigm_apx(zf);
                float gg = tanh_apx(zg);
                float og = sigm_apx(zo);
                float cv = fg * cst[s] + ig * gg;
                cst[s] = cv;
                float hv = og * tanh_apx(cv);
                hst[s] = hv;
                ob[s][toff] = hv;
                hw[hoff[s]] = __float2half(hv);
            }
            toff += NH;
            __syncthreads();
        };

        for (int t = 0; t < TT; t += 2) {
            step(t, xpa, xpb);
            step(t + 1, xpb, xpa);
        }

        // h_n, c_n: out = [output | h_n | c_n]
        float* hn = out + (size_t)BB * TT * NH;
        float* cn = hn + (size_t)BB * NH;
#pragma unroll
        for (int s = 0; s < 4; s++) {
            int jo = s >> 1, bo = s & 1;
            int j = j0 + jo * 8, b = bg0 + bo;
            hn[(size_t)b * NH + n * DH + j] = hst[s];
            cn[(size_t)b * NH + n * DH + j] = cst[s];
        }
    }
}

extern "C" void kernel_launch(void* const* d_in, const int* in_sizes, int n_in,
                              void* d_out, int out_size) {
    const float* x   = (const float*)d_in[0];
    const float* Wih = (const float*)d_in[1];
    const float* Whh = (const float*)d_in[2];
    const float* bih = (const float*)d_in[3];
    const float* bhh = (const float*)d_in[4];
    float* out = (float*)d_out;

    cudaFuncSetAttribute(wlstm_combo,
                         cudaFuncAttributeMaxDynamicSharedMemorySize, S_TOTAL);

    wlstm_combo<<<128, 256, S_TOTAL>>>(x, Wih, Whh, bih, bhh, out);
}

// round 16
// speedup vs baseline: 1.0738x; 1.0738x over previous
#include <cuda_runtime.h>
#include <cuda_fp16.h>
#include <cstdint>

// Problem dims
#define NL 16
#define DH 128
#define G4 512      // 4*H
#define BB 32
#define TT 512
#define NH 2048     // N*H
#define STRD 136    // padded halves per row (conflict-free LDS)

// x_proj scratch, GATE-INTERLEAVED: [n][t][b][j][gate] fp16, bias pre-added
__device__ __half g_xp16[(size_t)NL * TT * BB * G4];

// ---------------- mma.sync m16n8k16 (fp16 in, fp32 acc) ----------------
__device__ __forceinline__ void mma16816(float* d, const uint32_t* a,
                                         uint32_t b0, uint32_t b1) {
    asm volatile("mma.sync.aligned.m16n8k16.row.col.f32.f16.f16.f32 "
                 "{%0,%1,%2,%3}, {%4,%5,%6,%7}, {%8,%9}, {%0,%1,%2,%3};"
                 : "+f"(d[0]), "+f"(d[1]), "+f"(d[2]), "+f"(d[3])
                 : "r"(a[0]), "r"(a[1]), "r"(a[2]), "r"(a[3]), "r"(b0), "r"(b1));
}

// HW tanh (1 MUFU); sigma(x) = 0.5*tanh(x/2)+0.5
__device__ __forceinline__ float tanh_apx(float x) {
    float t;
    asm("tanh.approx.f32 %0, %1;" : "=f"(t) : "f"(x));
    return t;
}
__device__ __forceinline__ float sigm_apx(float x) {
    return fmaf(0.5f, tanh_apx(0.5f * x), 0.5f);
}

// =================================================================
// Phase 1 v3: x_proj16[n][t][b][j][g] = W_ih[n].x + b_ih + b_hh
// J-HALF split for occupancy 2: grid (8 hb, 2 gh, 16 n) = 256 CTAs,
// 256 threads, 2 CTAs/SM. CTA covers j in [gh*64, gh*64+64), all
// 4 gates (256 gate-rows), batches hb*4..+3, all t.
// SMEM/CTA = 112896 B -> two co-resident CTAs hide serial latency.
// =================================================================
#define STGW2 132   // stage row stride in words (128 + 4 pad)
#define P1_S_WS  0                         // W half [256][STRD] fp16 = 69632
#define P1_S_X   69632                     // x tile [128][STRD] fp16 = 34816
#define P1_S_STG 104448                    // stage [2][8][STGW2] words = 8448
#define P1_SMEM  112896

__global__ void __launch_bounds__(256, 2) wlstm_xproj(
    const float* __restrict__ x, const float* __restrict__ Wih,
    const float* __restrict__ bih, const float* __restrict__ bhh)
{
    extern __shared__ char p1smem[];
    __half*    ws  = (__half*)(p1smem + P1_S_WS);
    __half*    xs  = (__half*)(p1smem + P1_S_X);
    uint32_t*  stw = (uint32_t*)(p1smem + P1_S_STG);

    const int tid = threadIdx.x, wid = tid >> 5, lane = tid & 31;
    const int g0 = lane >> 2, cq = lane & 3;
    const int hb = blockIdx.x, gh = blockIdx.y, n = blockIdx.z;

    // ---- W half -> SMEM fp16: local row rl -> global row (rl>>6)*128 + gh*64 + (rl&63)
    const float* W = Wih + (size_t)n * G4 * DH;
#pragma unroll 4
    for (int i = tid; i < 256 * DH / 4; i += 256) {
        int rl = i >> 5, k = (i & 31) * 4;
        int R = ((rl >> 6) << 7) + gh * 64 + (rl & 63);
        float4 w = *(const float4*)(W + (size_t)R * DH + k);
        __half2 h01 = __floats2half2_rn(w.x, w.y);
        __half2 h23 = __floats2half2_rn(w.z, w.w);
        uint2 v = { *(uint32_t*)&h01, *(uint32_t*)&h23 };
        *(uint2*)(ws + rl * STRD + k) = v;
    }
    __syncthreads();

    // ---- A-fragments: warp wid owns local m-tiles {2wid, 2wid+1} (of 16)
    uint32_t a[2][8][4];
    const uint32_t* ws32 = (const uint32_t*)ws;
#pragma unroll
    for (int ti = 0; ti < 2; ti++) {
        int rl0 = (2 * wid + ti) * 16 + g0;
#pragma unroll
        for (int kc = 0; kc < 8; kc++) {
            int kw = kc * 8 + cq;
            a[ti][kc][0] = ws32[rl0 * (STRD / 2) + kw];
            a[ti][kc][1] = ws32[(rl0 + 8) * (STRD / 2) + kw];
            a[ti][kc][2] = ws32[rl0 * (STRD / 2) + kw + 4];
            a[ti][kc][3] = ws32[(rl0 + 8) * (STRD / 2) + kw + 4];
        }
    }
    // bias + stage offsets per ti
    float bsv[2][2];
    int soff[2];   // stage half-offset for row rl0 (jl*4 + gate)
#pragma unroll
    for (int ti = 0; ti < 2; ti++) {
        int rl0 = (2 * wid + ti) * 16 + g0;
        int R0 = ((rl0 >> 6) << 7) + gh * 64 + (rl0 & 63);
        int R1 = R0 + 8;
        bsv[ti][0] = bih[n * G4 + R0] + bhh[n * G4 + R0];
        bsv[ti][1] = bih[n * G4 + R1] + bhh[n * G4 + R1];
        soff[ti] = (rl0 & 63) * 4 + (rl0 >> 6);
    }

    for (int u = 0; u < 16; u++) {
        const int b = hb * 4 + (u >> 2), t0 = (u & 3) * 128;
        // ---- load x tile (single buffer; co-resident CTA hides the stall)
#pragma unroll 4
        for (int i = tid; i < 128 * DH / 4; i += 256) {
            int tl = i >> 5, c4 = (i & 31) * 4;
            float4 w = *(const float4*)(x + ((size_t)b * TT + t0 + tl) * NH + n * DH + c4);
            __half2 h01 = __floats2half2_rn(w.x, w.y);
            __half2 h23 = __floats2half2_rn(w.z, w.w);
            uint2 v = { *(uint32_t*)&h01, *(uint32_t*)&h23 };
            *(uint2*)(xs + tl * STRD + c4) = v;
        }
        __syncthreads();
        const uint32_t* xs32 = (const uint32_t*)xs;

        for (int nt = 0; nt < 16; nt++) {
            uint32_t* stg = stw + (nt & 1) * (8 * STGW2);
            __half*   sth = (__half*)stg;
            float d[2][4];
#pragma unroll
            for (int ti = 0; ti < 2; ti++)
#pragma unroll
                for (int q = 0; q < 4; q++) d[ti][q] = 0.0f;

            int col = nt * 8 + g0;
#pragma unroll
            for (int kc = 0; kc < 8; kc++) {
                uint32_t b0 = xs32[col * (STRD / 2) + kc * 8 + cq];
                uint32_t b1 = xs32[col * (STRD / 2) + kc * 8 + cq + 4];
#pragma unroll
                for (int ti = 0; ti < 2; ti++) mma16816(d[ti], a[ti][kc], b0, b1);
            }
            // stage slice [8 t][jl*4 + gate] with bias
            int tb0 = 2 * cq;
#pragma unroll
            for (int ti = 0; ti < 2; ti++) {
                sth[tb0 * (2 * STGW2) + soff[ti]]            = __float2half(d[ti][0] + bsv[ti][0]);
                sth[(tb0 + 1) * (2 * STGW2) + soff[ti]]      = __float2half(d[ti][1] + bsv[ti][0]);
                sth[tb0 * (2 * STGW2) + soff[ti] + 32]       = __float2half(d[ti][2] + bsv[ti][1]);
                sth[(tb0 + 1) * (2 * STGW2) + soff[ti] + 32] = __float2half(d[ti][3] + bsv[ti][1]);
            }
            __syncthreads();
            // coop store: 8 rows x 32 uint4 = 256, one per thread
            {
                int row = tid >> 5, w4 = tid & 31;
                uint4 v = *(const uint4*)(stg + row * STGW2 + w4 * 4);
                __half* dro = g_xp16 + ((size_t)(n * TT + t0 + nt * 8 + row) * BB + b) * G4
                              + gh * 256;
                *(uint4*)(dro + w4 * 8) = v;
            }
        }
        __syncthreads();   // stage + xs reads done before reuse
    }
}

// =================================================================
// Phase 2: persistent recurrence — EXACT R10 (best measured: 273us).
// grid 128 = n(16) x bc(8 of 4 batches), 256 threads (8 warps).
// Batches in EVEN mma N-cols; warp-local epilogue; 1 barrier/step.
// =================================================================
__global__ void __launch_bounds__(256, 1) wlstm_rec(
    const float* __restrict__ Whh, float* __restrict__ out)
{
    __shared__ __half hs[2][8][STRD];

    const int tid = threadIdx.x, wid = tid >> 5, lane = tid & 31;
    const int g0 = lane >> 2, cq = lane & 3;
    const int n = blockIdx.x >> 3, bc = blockIdx.x & 7;

    for (int i = tid; i < 2 * 8 * STRD; i += 256) ((__half*)hs)[i] = __float2half(0.0f);

    uint32_t a[4][8][4];
    const float* W = Whh + (size_t)n * G4 * DH;
#pragma unroll
    for (int gi = 0; gi < 4; gi++) {
        int r0 = gi * 128 + wid * 16 + g0;
#pragma unroll
        for (int kc = 0; kc < 8; kc++) {
            int k0 = kc * 16 + cq * 2;
            float2 w00 = *(const float2*)(W + (size_t)r0 * DH + k0);
            float2 w10 = *(const float2*)(W + (size_t)(r0 + 8) * DH + k0);
            float2 w01 = *(const float2*)(W + (size_t)r0 * DH + k0 + 8);
            float2 w11 = *(const float2*)(W + (size_t)(r0 + 8) * DH + k0 + 8);
            __half2 h00 = __floats2half2_rn(w00.x, w00.y);
            __half2 h10 = __floats2half2_rn(w10.x, w10.y);
            __half2 h01 = __floats2half2_rn(w01.x, w01.y);
            __half2 h11 = __floats2half2_rn(w11.x, w11.y);
            a[gi][kc][0] = *(uint32_t*)&h00;
            a[gi][kc][1] = *(uint32_t*)&h10;
            a[gi][kc][2] = *(uint32_t*)&h01;
            a[gi][kc][3] = *(uint32_t*)&h11;
        }
    }

    const int j0 = wid * 16 + g0;
    const int b  = bc * 4 + cq;

    const __half* xqb[2];
    float* ob[2];
    int hoff[2];
#pragma unroll
    for (int s = 0; s < 2; s++) {
        int j = j0 + s * 8;
        xqb[s] = g_xp16 + ((size_t)n * TT * BB + b) * G4 + j * 4;
        ob[s]  = out + (size_t)b * TT * NH + n * DH + j;
        hoff[s] = (2 * cq) * STRD + j;
    }

    uint2 xpa[2], xpb[2];
#pragma unroll
    for (int s = 0; s < 2; s++) xpa[s] = *(const uint2*)xqb[s];

    float cst[2] = {0.0f, 0.0f}, hst[2] = {0.0f, 0.0f};

    __syncthreads();

    size_t toff = 0;

    auto step = [&](int t, uint2 (&xpc)[2], uint2 (&xpn)[2]) {
        if (t + 1 < TT) {
            size_t xo = (size_t)(t + 1) * (BB * G4);
#pragma unroll
            for (int s = 0; s < 2; s++) xpn[s] = *(const uint2*)(xqb[s] + xo);
        }
        const uint32_t* hb = (const uint32_t*)hs[t & 1];
        float d[4][4];
#pragma unroll
        for (int gi = 0; gi < 4; gi++)
#pragma unroll
            for (int q = 0; q < 4; q++) d[gi][q] = 0.0f;
#pragma unroll
        for (int kc = 0; kc < 8; kc++) {
            uint32_t b0 = hb[g0 * (STRD / 2) + kc * 8 + cq];
            uint32_t b1 = hb[g0 * (STRD / 2) + kc * 8 + cq + 4];
#pragma unroll
            for (int gi = 0; gi < 4; gi++) mma16816(d[gi], a[gi][kc], b0, b1);
        }

        __half* hw = (__half*)hs[(t + 1) & 1];
#pragma unroll
        for (int s = 0; s < 2; s++) {
            int q = s * 2;
            float2 f01 = __half22float2(*(__half2*)&xpc[s].x);
            float2 f23 = __half22float2(*(__half2*)&xpc[s].y);
            float zi = d[0][q] + f01.x;
            float zf = d[1][q] + f01.y;
            float zg = d[2][q] + f23.x;
            float zo = d[3][q] + f23.y;
            float ig = sigm_apx(zi);
            float fg = sigm_apx(zf);
            float gg = tanh_apx(zg);
            float og = sigm_apx(zo);
            float cv = fg * cst[s] + ig * gg;
            cst[s] = cv;
            float hv = og * tanh_apx(cv);
            hst[s] = hv;
            ob[s][toff] = hv;
            hw[hoff[s]] = __float2half(hv);
        }
        toff += NH;
        __syncthreads();
    };

    for (int t = 0; t < TT; t += 2) {
        step(t, xpa, xpb);
        step(t + 1, xpb, xpa);
    }

    float* hn = out + (size_t)BB * TT * NH;
    float* cn = hn + (size_t)BB * NH;
#pragma unroll
    for (int s = 0; s < 2; s++) {
        int j = j0 + s * 8;
        hn[(size_t)b * NH + n * DH + j] = hst[s];
        cn[(size_t)b * NH + n * DH + j] = cst[s];
    }
}

extern "C" void kernel_launch(void* const* d_in, const int* in_sizes, int n_in,
                              void* d_out, int out_size) {
    const float* x   = (const float*)d_in[0];
    const float* Wih = (const float*)d_in[1];
    const float* Whh = (const float*)d_in[2];
    const float* bih = (const float*)d_in[3];
    const float* bhh = (const float*)d_in[4];
    float* out = (float*)d_out;

    cudaFuncSetAttribute(wlstm_xproj,
                         cudaFuncAttributeMaxDynamicSharedMemorySize, P1_SMEM);

    dim3 g1(8, 2, NL);   // 256 CTAs, 2 per SM
    wlstm_xproj<<<g1, 256, P1_SMEM>>>(x, Wih, bih, bhh);
    wlstm_rec<<<NL * 8, 256>>>(Whh, out);
}